// round 1
// baseline (speedup 1.0000x reference)
#include <cuda_runtime.h>
#include <math.h>

// Problem constants
#define B_   2
#define S_   2048
#define D_   1024
#define H_   16
#define DK_  64
#define MTOT (B_ * S_)   // 4096

// 64 MB scratch: Q | K | V | Attn  (each MTOT x D_ fp32)
__device__ float g_scratch[4ull * MTOT * D_];

// ============================================================================
// GEMM (NT): C[M,N] = A[M,K] @ W[N,K]^T + bias[N]
// 128x128 tile, BK=16, 256 threads, 8x8 per-thread register tile.
// Smem tiles stored K-outer/transposed so compute reads are float4 + conflict-free.
// ============================================================================
#define BM 128
#define BN 128
#define BK 16
#define PAD 4

__global__ __launch_bounds__(256) void gemm_nt_bias(
    const float* __restrict__ A, const float* __restrict__ W,
    const float* __restrict__ bias, float* __restrict__ C,
    int M, int N, int K)
{
    __shared__ float As[BK][BM + PAD];   // As[k][m]
    __shared__ float Bs[BK][BN + PAD];   // Bs[k][n]

    const int tid = threadIdx.x;
    const int tx = tid & 15;
    const int ty = tid >> 4;

    const float* Ab = A + (size_t)blockIdx.y * BM * K;
    const float* Wb = W + (size_t)blockIdx.x * BN * K;

    // loader mapping: 128 rows x 16 k  = 512 float4; 2 per thread
    const int lrow = tid >> 2;   // 0..63
    const int lk4  = tid & 3;    // float4 index within the 16-wide k slab

    float4 rA[2], rB[2];
    #pragma unroll
    for (int it = 0; it < 2; it++) {
        int row = lrow + it * 64;
        rA[it] = *(const float4*)(Ab + (size_t)row * K + lk4 * 4);
        rB[it] = *(const float4*)(Wb + (size_t)row * K + lk4 * 4);
    }

    float acc[8][8];
    #pragma unroll
    for (int i = 0; i < 8; i++)
        #pragma unroll
        for (int j = 0; j < 8; j++) acc[i][j] = 0.0f;

    for (int kt = 0; kt < K; kt += BK) {
        // commit staged regs to smem (transposed)
        #pragma unroll
        for (int it = 0; it < 2; it++) {
            int row = lrow + it * 64;
            As[lk4 * 4 + 0][row] = rA[it].x;
            As[lk4 * 4 + 1][row] = rA[it].y;
            As[lk4 * 4 + 2][row] = rA[it].z;
            As[lk4 * 4 + 3][row] = rA[it].w;
            Bs[lk4 * 4 + 0][row] = rB[it].x;
            Bs[lk4 * 4 + 1][row] = rB[it].y;
            Bs[lk4 * 4 + 2][row] = rB[it].z;
            Bs[lk4 * 4 + 3][row] = rB[it].w;
        }
        __syncthreads();

        // prefetch next slab into regs (hide LDG under FMA)
        if (kt + BK < K) {
            #pragma unroll
            for (int it = 0; it < 2; it++) {
                int row = lrow + it * 64;
                rA[it] = *(const float4*)(Ab + (size_t)row * K + kt + BK + lk4 * 4);
                rB[it] = *(const float4*)(Wb + (size_t)row * K + kt + BK + lk4 * 4);
            }
        }

        #pragma unroll
        for (int k = 0; k < BK; k++) {
            float4 a0 = *(const float4*)&As[k][ty * 8];
            float4 a1 = *(const float4*)&As[k][ty * 8 + 4];
            float4 b0 = *(const float4*)&Bs[k][tx * 8];
            float4 b1 = *(const float4*)&Bs[k][tx * 8 + 4];
            float ar[8] = {a0.x, a0.y, a0.z, a0.w, a1.x, a1.y, a1.z, a1.w};
            float br[8] = {b0.x, b0.y, b0.z, b0.w, b1.x, b1.y, b1.z, b1.w};
            #pragma unroll
            for (int i = 0; i < 8; i++)
                #pragma unroll
                for (int j = 0; j < 8; j++)
                    acc[i][j] += ar[i] * br[j];
        }
        __syncthreads();
    }

    const int row0 = blockIdx.y * BM + ty * 8;
    const int col0 = blockIdx.x * BN + tx * 8;
    float4 bv0 = *(const float4*)(bias + col0);
    float4 bv1 = *(const float4*)(bias + col0 + 4);
    #pragma unroll
    for (int i = 0; i < 8; i++) {
        float4 o0 = make_float4(acc[i][0] + bv0.x, acc[i][1] + bv0.y,
                                acc[i][2] + bv0.z, acc[i][3] + bv0.w);
        float4 o1 = make_float4(acc[i][4] + bv1.x, acc[i][5] + bv1.y,
                                acc[i][6] + bv1.z, acc[i][7] + bv1.w);
        *(float4*)(C + (size_t)(row0 + i) * N + col0)     = o0;
        *(float4*)(C + (size_t)(row0 + i) * N + col0 + 4) = o1;
    }
}

// ============================================================================
// Flash attention (causal), fp32. One block = 64 query rows x one head.
// Smem: QsT[d][r], KsT[d][c] (reused as PsT[c][r]), Vs[c][d]; stride 68.
// Thread (ty,tx) in 16x16 grid: rows ty*4..+3, cols/dims tx*4..+3.
// ============================================================================
#define FT 64
#define FP 68
#define FSM_BYTES (3 * FT * FP * 4)   // 52224

__global__ __launch_bounds__(256) void flash_attn(
    const float* __restrict__ Qg, const float* __restrict__ Kg,
    const float* __restrict__ Vg, float* __restrict__ Og)
{
    extern __shared__ float sm[];
    float* QsT = sm;                // [FT][FP]  (d-major)
    float* KsT = sm + FT * FP;      // [FT][FP]  (d-major), reused as PsT[c][r]
    float* Vs  = sm + 2 * FT * FP;  // [FT][FP]  (c-major, natural)

    const int tid = threadIdx.x;
    const int tx = tid & 15;
    const int ty = tid >> 4;
    const int qb = blockIdx.x;   // query tile 0..31
    const int h  = blockIdx.y;
    const int b  = blockIdx.z;

    const float scale = 0.125f;  // 1/sqrt(DK)

    // Load Q tile, transposed to d-major, pre-scaled
    const float* Qbase = Qg + ((size_t)(b * S_ + qb * FT)) * D_ + h * DK_;
    #pragma unroll
    for (int it = 0; it < 4; it++) {
        int li = tid + it * 256;
        int r = li >> 4, d4 = li & 15;
        float4 f = *(const float4*)(Qbase + (size_t)r * D_ + d4 * 4);
        QsT[(d4 * 4 + 0) * FP + r] = f.x * scale;
        QsT[(d4 * 4 + 1) * FP + r] = f.y * scale;
        QsT[(d4 * 4 + 2) * FP + r] = f.z * scale;
        QsT[(d4 * 4 + 3) * FP + r] = f.w * scale;
    }

    float m_i[4], l_i[4], acc[4][4];
    #pragma unroll
    for (int i = 0; i < 4; i++) {
        m_i[i] = -1e30f;
        l_i[i] = 0.0f;
        #pragma unroll
        for (int j = 0; j < 4; j++) acc[i][j] = 0.0f;
    }

    for (int t = 0; t <= qb; t++) {
        __syncthreads();   // protect KsT/Vs reuse across iterations
        const float* Kbase = Kg + ((size_t)(b * S_ + t * FT)) * D_ + h * DK_;
        const float* Vbase = Vg + ((size_t)(b * S_ + t * FT)) * D_ + h * DK_;
        #pragma unroll
        for (int it = 0; it < 4; it++) {
            int li = tid + it * 256;
            int c = li >> 4, d4 = li & 15;
            float4 f = *(const float4*)(Kbase + (size_t)c * D_ + d4 * 4);
            KsT[(d4 * 4 + 0) * FP + c] = f.x;
            KsT[(d4 * 4 + 1) * FP + c] = f.y;
            KsT[(d4 * 4 + 2) * FP + c] = f.z;
            KsT[(d4 * 4 + 3) * FP + c] = f.w;
            float4 g = *(const float4*)(Vbase + (size_t)c * D_ + d4 * 4);
            *(float4*)&Vs[c * FP + d4 * 4] = g;
        }
        __syncthreads();

        // scores: S = Q K^T (4x4 per thread)
        float s[4][4];
        #pragma unroll
        for (int i = 0; i < 4; i++)
            #pragma unroll
            for (int j = 0; j < 4; j++) s[i][j] = 0.0f;

        #pragma unroll 8
        for (int d = 0; d < FT; d++) {
            float4 q4 = *(const float4*)&QsT[d * FP + ty * 4];
            float4 k4 = *(const float4*)&KsT[d * FP + tx * 4];
            float qr[4] = {q4.x, q4.y, q4.z, q4.w};
            float kr[4] = {k4.x, k4.y, k4.z, k4.w};
            #pragma unroll
            for (int i = 0; i < 4; i++)
                #pragma unroll
                for (int j = 0; j < 4; j++)
                    s[i][j] += qr[i] * kr[j];
        }

        // causal mask only on diagonal tile
        if (t == qb) {
            #pragma unroll
            for (int i = 0; i < 4; i++)
                #pragma unroll
                for (int j = 0; j < 4; j++)
                    if (tx * 4 + j > ty * 4 + i) s[i][j] = -1e30f;
        }

        // online softmax: row reductions across the 16 lanes sharing each row
        #pragma unroll
        for (int i = 0; i < 4; i++) {
            float tm = fmaxf(fmaxf(s[i][0], s[i][1]), fmaxf(s[i][2], s[i][3]));
            #pragma unroll
            for (int off = 8; off >= 1; off >>= 1)
                tm = fmaxf(tm, __shfl_xor_sync(0xffffffffu, tm, off));
            float mnew = fmaxf(m_i[i], tm);
            float al = __expf(m_i[i] - mnew);
            float ps = 0.0f;
            #pragma unroll
            for (int j = 0; j < 4; j++) {
                float p = __expf(s[i][j] - mnew);
                s[i][j] = p;
                ps += p;
            }
            #pragma unroll
            for (int off = 8; off >= 1; off >>= 1)
                ps += __shfl_xor_sync(0xffffffffu, ps, off);
            l_i[i] = l_i[i] * al + ps;
            m_i[i] = mnew;
            #pragma unroll
            for (int j = 0; j < 4; j++) acc[i][j] *= al;
        }

        __syncthreads();   // all lanes done reading KsT (scores)
        // stage P (c-major) into the dead K buffer
        #pragma unroll
        for (int i = 0; i < 4; i++)
            #pragma unroll
            for (int j = 0; j < 4; j++)
                KsT[(tx * 4 + j) * FP + ty * 4 + i] = s[i][j];
        __syncthreads();

        // acc += P @ V  (4x4 per thread)
        #pragma unroll 8
        for (int c = 0; c < FT; c++) {
            float4 p4 = *(const float4*)&KsT[c * FP + ty * 4];
            float4 v4 = *(const float4*)&Vs[c * FP + tx * 4];
            float pr[4] = {p4.x, p4.y, p4.z, p4.w};
            float vr[4] = {v4.x, v4.y, v4.z, v4.w};
            #pragma unroll
            for (int i = 0; i < 4; i++)
                #pragma unroll
                for (int j = 0; j < 4; j++)
                    acc[i][j] += pr[i] * vr[j];
        }
    }

    // normalize + write out (row-major, per-head column slice)
    float* Obase = Og + ((size_t)(b * S_ + qb * FT)) * D_ + h * DK_;
    #pragma unroll
    for (int i = 0; i < 4; i++) {
        float inv = 1.0f / l_i[i];
        float4 o = make_float4(acc[i][0] * inv, acc[i][1] * inv,
                               acc[i][2] * inv, acc[i][3] * inv);
        *(float4*)(Obase + (size_t)(ty * 4 + i) * D_ + tx * 4) = o;
    }
}

// ============================================================================
// Launch
// ============================================================================
extern "C" void kernel_launch(void* const* d_in, const int* in_sizes, int n_in,
                              void* d_out, int out_size)
{
    const float* X  = (const float*)d_in[0];
    const float* Wq = (const float*)d_in[1];
    const float* bq = (const float*)d_in[2];
    const float* Wk = (const float*)d_in[3];
    const float* bk = (const float*)d_in[4];
    const float* Wv = (const float*)d_in[5];
    const float* bv = (const float*)d_in[6];
    const float* Wo = (const float*)d_in[7];
    const float* bo = (const float*)d_in[8];
    // d_in[9] = causal mask (structure known, ignored)
    float* out = (float*)d_out;

    float* scratch = nullptr;
    cudaGetSymbolAddress((void**)&scratch, g_scratch);
    float* Qs = scratch;
    float* Ks = scratch + (size_t)MTOT * D_;
    float* Vs = scratch + 2ull * MTOT * D_;
    float* As = scratch + 3ull * MTOT * D_;

    cudaFuncSetAttribute(flash_attn, cudaFuncAttributeMaxDynamicSharedMemorySize, FSM_BYTES);

    dim3 gg(D_ / BN, MTOT / BM);
    gemm_nt_bias<<<gg, 256>>>(X, Wq, bq, Qs, MTOT, D_, D_);
    gemm_nt_bias<<<gg, 256>>>(X, Wk, bk, Ks, MTOT, D_, D_);
    gemm_nt_bias<<<gg, 256>>>(X, Wv, bv, Vs, MTOT, D_, D_);

    flash_attn<<<dim3(S_ / FT, H_, B_), 256, FSM_BYTES>>>(Qs, Ks, Vs, As);

    gemm_nt_bias<<<gg, 256>>>(As, Wo, bo, out, MTOT, D_, D_);
}

// round 3
// speedup vs baseline: 1.3297x; 1.3297x over previous
#include <cuda_runtime.h>
#include <cuda_bf16.h>
#include <math.h>
#include <stdint.h>

// Problem constants
#define B_   2
#define S_   2048
#define D_   1024
#define H_   16
#define DK_  64
#define MTOT (B_ * S_)   // 4096

// fp32 scratch: Q | K | V | Attn
__device__ float g_qkva[4ull * MTOT * D_];
// bf16 hi/lo splits
__device__ __nv_bfloat16 g_ahi[(size_t)MTOT * D_];
__device__ __nv_bfloat16 g_alo[(size_t)MTOT * D_];
__device__ __nv_bfloat16 g_whi[4][(size_t)D_ * D_];
__device__ __nv_bfloat16 g_wlo[4][(size_t)D_ * D_];

// ============================================================================
// PTX helpers (base sm_100-safe: cp.async / ldmatrix / mma.sync only)
// ============================================================================
__device__ __forceinline__ uint32_t smem_u32(const void* p) {
    return (uint32_t)__cvta_generic_to_shared(p);
}

#define CP_ASYNC16(dst, src) \
    asm volatile("cp.async.cg.shared.global [%0], [%1], 16;" :: "r"(dst), "l"(src))
#define CP_COMMIT() asm volatile("cp.async.commit_group;")
#define CP_WAIT1()  asm volatile("cp.async.wait_group 1;")
#define CP_WAIT0()  asm volatile("cp.async.wait_group 0;")

#define LDSM_X4(r, addr)                                                     \
    asm volatile("ldmatrix.sync.aligned.m8n8.x4.shared.b16 {%0,%1,%2,%3}, [%4];" \
                 : "=r"((r)[0]), "=r"((r)[1]), "=r"((r)[2]), "=r"((r)[3])    \
                 : "r"(addr))

#define MMA16816(d, a, b0v, b1v)                                             \
    asm volatile("mma.sync.aligned.m16n8k16.row.col.f32.bf16.bf16.f32 "     \
                 "{%0,%1,%2,%3}, {%4,%5,%6,%7}, {%8,%9}, {%0,%1,%2,%3};"    \
                 : "+f"((d)[0]), "+f"((d)[1]), "+f"((d)[2]), "+f"((d)[3])   \
                 : "r"((a)[0]), "r"((a)[1]), "r"((a)[2]), "r"((a)[3]),      \
                   "r"(b0v), "r"(b1v))

// ============================================================================
// hi/lo bf16 split:  x = hi + lo,  hi = bf16(x), lo = bf16(x - hi)
// ============================================================================
__global__ void split_bf16(const float* __restrict__ src,
                           __nv_bfloat16* __restrict__ hi,
                           __nv_bfloat16* __restrict__ lo, int n)
{
    int i = (blockIdx.x * blockDim.x + threadIdx.x) * 4;
    if (i >= n) return;
    float4 v = *(const float4*)(src + i);
    float f[4] = {v.x, v.y, v.z, v.w};
    __nv_bfloat162 h2[2], l2[2];
    #pragma unroll
    for (int p = 0; p < 2; p++) {
        __nv_bfloat16 h0 = __float2bfloat16(f[2*p]);
        __nv_bfloat16 h1 = __float2bfloat16(f[2*p+1]);
        __nv_bfloat16 l0 = __float2bfloat16(f[2*p]   - __bfloat162float(h0));
        __nv_bfloat16 l1 = __float2bfloat16(f[2*p+1] - __bfloat162float(h1));
        h2[p] = __nv_bfloat162(h0, h1);
        l2[p] = __nv_bfloat162(l0, l1);
    }
    *(uint2*)(hi + i) = *(uint2*)h2;
    *(uint2*)(lo + i) = *(uint2*)l2;
}

// ============================================================================
// mma.sync GEMM:  C[4096,1024] = A @ W^T + bias, 3-term bf16 split.
// CTA 128x128, 8 warps (2x4), warp tile 64x32, BK=32, cp.async double buffer.
// Smem tile layout per matrix: [kk(2)][row(128)][32B], 16B granule swizzled by
// g ^= (r>>2)&1  -> conflict-free ldmatrix.x4.
// ============================================================================
#define GBK        32
#define TILE_B     8192          // one matrix tile: 2*128*32 bytes
#define STAGE_B    (4 * TILE_B)  // Ahi|Alo|Whi|Wlo = 32768
#define GSM_BYTES  (2 * STAGE_B + 256)

__global__ __launch_bounds__(256) void gemm_mma(
    const __nv_bfloat16* __restrict__ Ahi, const __nv_bfloat16* __restrict__ Alo,
    const __nv_bfloat16* __restrict__ Whi, const __nv_bfloat16* __restrict__ Wlo,
    const float* __restrict__ bias, float* __restrict__ C)
{
    extern __shared__ char dsm[];
    const uint32_t smbase = (smem_u32(dsm) + 127u) & ~127u;

    const int tid  = threadIdx.x;
    const int lane = tid & 31;
    const int wid  = tid >> 5;
    const int wm   = wid >> 2;      // 0..1
    const int wn   = wid & 3;       // 0..3
    const int row0 = blockIdx.y * 128;
    const int col0 = blockIdx.x * 128;

    const __nv_bfloat16* srcs[4] = {
        Ahi + (size_t)row0 * D_, Alo + (size_t)row0 * D_,
        Whi + (size_t)col0 * D_, Wlo + (size_t)col0 * D_
    };

    // per-thread load mapping (8 x 16B granules per stage)
    int l_tile[8], l_r[8], l_kk[8], l_g[8];
    uint32_t l_dst[8];
    #pragma unroll
    for (int t = 0; t < 8; t++) {
        int idx = tid + t * 256;
        l_tile[t] = idx >> 9;
        int i = idx & 511;
        l_r[t]  = i >> 2;
        l_kk[t] = (i >> 1) & 1;
        l_g[t]  = i & 1;
        int gsw = l_g[t] ^ ((l_r[t] >> 2) & 1);
        l_dst[t] = (uint32_t)(l_tile[t] * TILE_B + l_kk[t] * 4096 + l_r[t] * 32 + gsw * 16);
    }

    float acc[4][4][4];
    #pragma unroll
    for (int mi = 0; mi < 4; mi++)
        #pragma unroll
        for (int nj = 0; nj < 4; nj++)
            #pragma unroll
            for (int e = 0; e < 4; e++) acc[mi][nj][e] = 0.0f;

    // ldmatrix per-lane source offsets (within a [128][32B] chunk)
    const int lr = lane & 15;      // row within 16-row group
    const int lg = lane >> 4;      // granule 0/1

    // prologue: stage 0
    #pragma unroll
    for (int t = 0; t < 8; t++) {
        const __nv_bfloat16* gp = srcs[l_tile[t]] +
            (size_t)l_r[t] * D_ + l_kk[t] * 16 + l_g[t] * 8;
        CP_ASYNC16(smbase + l_dst[t], gp);
    }
    CP_COMMIT();

    const int NIT = D_ / GBK;   // 32
    for (int it = 0; it < NIT; it++) {
        const int s = it & 1;
        if (it + 1 < NIT) {
            const uint32_t sb = smbase + ((it + 1) & 1) * STAGE_B;
            #pragma unroll
            for (int t = 0; t < 8; t++) {
                const __nv_bfloat16* gp = srcs[l_tile[t]] +
                    (size_t)l_r[t] * D_ + (it + 1) * GBK + l_kk[t] * 16 + l_g[t] * 8;
                CP_ASYNC16(sb + l_dst[t], gp);
            }
            CP_COMMIT();
            CP_WAIT1();
        } else {
            CP_WAIT0();
        }
        __syncthreads();

        const uint32_t stg = smbase + s * STAGE_B;
        #pragma unroll
        for (int kk = 0; kk < 2; kk++) {
            uint32_t a_hi[4][4], a_lo[4][4];
            #pragma unroll
            for (int mi = 0; mi < 4; mi++) {
                int r = wm * 64 + mi * 16 + lr;
                uint32_t off = (uint32_t)(kk * 4096 + r * 32 + ((lg ^ ((r >> 2) & 1)) * 16));
                LDSM_X4(a_hi[mi], stg + 0 * TILE_B + off);
                LDSM_X4(a_lo[mi], stg + 1 * TILE_B + off);
            }
            uint32_t b_hi[2][4], b_lo[2][4];
            #pragma unroll
            for (int ni = 0; ni < 2; ni++) {
                int r = wn * 32 + ni * 16 + lr;
                uint32_t off = (uint32_t)(kk * 4096 + r * 32 + ((lg ^ ((r >> 2) & 1)) * 16));
                LDSM_X4(b_hi[ni], stg + 2 * TILE_B + off);
                LDSM_X4(b_lo[ni], stg + 3 * TILE_B + off);
            }
            #pragma unroll
            for (int mi = 0; mi < 4; mi++) {
                #pragma unroll
                for (int nj = 0; nj < 4; nj++) {
                    const int ni = nj >> 1, sel = nj & 1;
                    MMA16816(acc[mi][nj], a_hi[mi], b_hi[ni][sel], b_hi[ni][sel + 2]);
                    MMA16816(acc[mi][nj], a_hi[mi], b_lo[ni][sel], b_lo[ni][sel + 2]);
                    MMA16816(acc[mi][nj], a_lo[mi], b_hi[ni][sel], b_hi[ni][sel + 2]);
                }
            }
        }
        __syncthreads();
    }

    // epilogue: acc + bias -> C
    const int qr = lane >> 2;          // 0..7
    const int qc = (lane & 3) * 2;     // 0,2,4,6
    #pragma unroll
    for (int nj = 0; nj < 4; nj++) {
        const int c = col0 + wn * 32 + nj * 8 + qc;
        const float2 bv = *(const float2*)(bias + c);
        #pragma unroll
        for (int mi = 0; mi < 4; mi++) {
            const int r = row0 + wm * 64 + mi * 16 + qr;
            float2 o0 = make_float2(acc[mi][nj][0] + bv.x, acc[mi][nj][1] + bv.y);
            float2 o1 = make_float2(acc[mi][nj][2] + bv.x, acc[mi][nj][3] + bv.y);
            *(float2*)(C + (size_t)r * D_ + c)       = o0;
            *(float2*)(C + (size_t)(r + 8) * D_ + c) = o1;
        }
    }
}

// ============================================================================
// Flash attention (causal), fp32 — unchanged (Round 1, 702us).
// ============================================================================
#define FT 64
#define FP 68
#define FSM_BYTES (3 * FT * FP * 4)

__global__ __launch_bounds__(256) void flash_attn(
    const float* __restrict__ Qg, const float* __restrict__ Kg,
    const float* __restrict__ Vg, float* __restrict__ Og)
{
    extern __shared__ float sm[];
    float* QsT = sm;
    float* KsT = sm + FT * FP;
    float* Vs  = sm + 2 * FT * FP;

    const int tid = threadIdx.x;
    const int tx = tid & 15;
    const int ty = tid >> 4;
    const int qb = blockIdx.x;
    const int h  = blockIdx.y;
    const int b  = blockIdx.z;

    const float scale = 0.125f;

    const float* Qbase = Qg + ((size_t)(b * S_ + qb * FT)) * D_ + h * DK_;
    #pragma unroll
    for (int it = 0; it < 4; it++) {
        int li = tid + it * 256;
        int r = li >> 4, d4 = li & 15;
        float4 f = *(const float4*)(Qbase + (size_t)r * D_ + d4 * 4);
        QsT[(d4 * 4 + 0) * FP + r] = f.x * scale;
        QsT[(d4 * 4 + 1) * FP + r] = f.y * scale;
        QsT[(d4 * 4 + 2) * FP + r] = f.z * scale;
        QsT[(d4 * 4 + 3) * FP + r] = f.w * scale;
    }

    float m_i[4], l_i[4], acc[4][4];
    #pragma unroll
    for (int i = 0; i < 4; i++) {
        m_i[i] = -1e30f;
        l_i[i] = 0.0f;
        #pragma unroll
        for (int j = 0; j < 4; j++) acc[i][j] = 0.0f;
    }

    for (int t = 0; t <= qb; t++) {
        __syncthreads();
        const float* Kbase = Kg + ((size_t)(b * S_ + t * FT)) * D_ + h * DK_;
        const float* Vbase = Vg + ((size_t)(b * S_ + t * FT)) * D_ + h * DK_;
        #pragma unroll
        for (int it = 0; it < 4; it++) {
            int li = tid + it * 256;
            int c = li >> 4, d4 = li & 15;
            float4 f = *(const float4*)(Kbase + (size_t)c * D_ + d4 * 4);
            KsT[(d4 * 4 + 0) * FP + c] = f.x;
            KsT[(d4 * 4 + 1) * FP + c] = f.y;
            KsT[(d4 * 4 + 2) * FP + c] = f.z;
            KsT[(d4 * 4 + 3) * FP + c] = f.w;
            float4 g = *(const float4*)(Vbase + (size_t)c * D_ + d4 * 4);
            *(float4*)&Vs[c * FP + d4 * 4] = g;
        }
        __syncthreads();

        float s[4][4];
        #pragma unroll
        for (int i = 0; i < 4; i++)
            #pragma unroll
            for (int j = 0; j < 4; j++) s[i][j] = 0.0f;

        #pragma unroll 8
        for (int d = 0; d < FT; d++) {
            float4 q4 = *(const float4*)&QsT[d * FP + ty * 4];
            float4 k4 = *(const float4*)&KsT[d * FP + tx * 4];
            float qr[4] = {q4.x, q4.y, q4.z, q4.w};
            float kr[4] = {k4.x, k4.y, k4.z, k4.w};
            #pragma unroll
            for (int i = 0; i < 4; i++)
                #pragma unroll
                for (int j = 0; j < 4; j++)
                    s[i][j] += qr[i] * kr[j];
        }

        if (t == qb) {
            #pragma unroll
            for (int i = 0; i < 4; i++)
                #pragma unroll
                for (int j = 0; j < 4; j++)
                    if (tx * 4 + j > ty * 4 + i) s[i][j] = -1e30f;
        }

        #pragma unroll
        for (int i = 0; i < 4; i++) {
            float tm = fmaxf(fmaxf(s[i][0], s[i][1]), fmaxf(s[i][2], s[i][3]));
            #pragma unroll
            for (int off = 8; off >= 1; off >>= 1)
                tm = fmaxf(tm, __shfl_xor_sync(0xffffffffu, tm, off));
            float mnew = fmaxf(m_i[i], tm);
            float al = __expf(m_i[i] - mnew);
            float ps = 0.0f;
            #pragma unroll
            for (int j = 0; j < 4; j++) {
                float p = __expf(s[i][j] - mnew);
                s[i][j] = p;
                ps += p;
            }
            #pragma unroll
            for (int off = 8; off >= 1; off >>= 1)
                ps += __shfl_xor_sync(0xffffffffu, ps, off);
            l_i[i] = l_i[i] * al + ps;
            m_i[i] = mnew;
            #pragma unroll
            for (int j = 0; j < 4; j++) acc[i][j] *= al;
        }

        __syncthreads();
        #pragma unroll
        for (int i = 0; i < 4; i++)
            #pragma unroll
            for (int j = 0; j < 4; j++)
                KsT[(tx * 4 + j) * FP + ty * 4 + i] = s[i][j];
        __syncthreads();

        #pragma unroll 8
        for (int c = 0; c < FT; c++) {
            float4 p4 = *(const float4*)&KsT[c * FP + ty * 4];
            float4 v4 = *(const float4*)&Vs[c * FP + tx * 4];
            float pr[4] = {p4.x, p4.y, p4.z, p4.w};
            float vr[4] = {v4.x, v4.y, v4.z, v4.w};
            #pragma unroll
            for (int i = 0; i < 4; i++)
                #pragma unroll
                for (int j = 0; j < 4; j++)
                    acc[i][j] += pr[i] * vr[j];
        }
    }

    float* Obase = Og + ((size_t)(b * S_ + qb * FT)) * D_ + h * DK_;
    #pragma unroll
    for (int i = 0; i < 4; i++) {
        float inv = 1.0f / l_i[i];
        float4 o = make_float4(acc[i][0] * inv, acc[i][1] * inv,
                               acc[i][2] * inv, acc[i][3] * inv);
        *(float4*)(Obase + (size_t)(ty * 4 + i) * D_ + tx * 4) = o;
    }
}

// ============================================================================
// Launch
// ============================================================================
extern "C" void kernel_launch(void* const* d_in, const int* in_sizes, int n_in,
                              void* d_out, int out_size)
{
    const float* X  = (const float*)d_in[0];
    const float* Wq = (const float*)d_in[1];
    const float* bq = (const float*)d_in[2];
    const float* Wk = (const float*)d_in[3];
    const float* bk = (const float*)d_in[4];
    const float* Wv = (const float*)d_in[5];
    const float* bv = (const float*)d_in[6];
    const float* Wo = (const float*)d_in[7];
    const float* bo = (const float*)d_in[8];
    float* out = (float*)d_out;

    float* qkva = nullptr;
    __nv_bfloat16 *ahi = nullptr, *alo = nullptr, *whi = nullptr, *wlo = nullptr;
    cudaGetSymbolAddress((void**)&qkva, g_qkva);
    cudaGetSymbolAddress((void**)&ahi, g_ahi);
    cudaGetSymbolAddress((void**)&alo, g_alo);
    cudaGetSymbolAddress((void**)&whi, g_whi);
    cudaGetSymbolAddress((void**)&wlo, g_wlo);

    float* Qs = qkva;
    float* Ks = qkva + (size_t)MTOT * D_;
    float* Vs = qkva + 2ull * MTOT * D_;
    float* As = qkva + 3ull * MTOT * D_;

    cudaFuncSetAttribute(gemm_mma, cudaFuncAttributeMaxDynamicSharedMemorySize, GSM_BYTES);
    cudaFuncSetAttribute(flash_attn, cudaFuncAttributeMaxDynamicSharedMemorySize, FSM_BYTES);

    const size_t WSZ = (size_t)D_ * D_;
    const int nX = MTOT * D_;
    const int nW = D_ * D_;

    split_bf16<<<nX / 1024, 256>>>(X, ahi, alo, nX);
    split_bf16<<<nW / 1024, 256>>>(Wq, whi + 0 * WSZ, wlo + 0 * WSZ, nW);
    split_bf16<<<nW / 1024, 256>>>(Wk, whi + 1 * WSZ, wlo + 1 * WSZ, nW);
    split_bf16<<<nW / 1024, 256>>>(Wv, whi + 2 * WSZ, wlo + 2 * WSZ, nW);
    split_bf16<<<nW / 1024, 256>>>(Wo, whi + 3 * WSZ, wlo + 3 * WSZ, nW);

    dim3 gg(D_ / 128, MTOT / 128);   // (8, 32)
    gemm_mma<<<gg, 256, GSM_BYTES>>>(ahi, alo, whi + 0 * WSZ, wlo + 0 * WSZ, bq, Qs);
    gemm_mma<<<gg, 256, GSM_BYTES>>>(ahi, alo, whi + 1 * WSZ, wlo + 1 * WSZ, bk, Ks);
    gemm_mma<<<gg, 256, GSM_BYTES>>>(ahi, alo, whi + 2 * WSZ, wlo + 2 * WSZ, bv, Vs);

    flash_attn<<<dim3(S_ / FT, H_, B_), 256, FSM_BYTES>>>(Qs, Ks, Vs, As);

    split_bf16<<<nX / 1024, 256>>>(As, ahi, alo, nX);
    gemm_mma<<<gg, 256, GSM_BYTES>>>(ahi, alo, whi + 3 * WSZ, wlo + 3 * WSZ, bo, out);
}

// round 4
// speedup vs baseline: 2.2579x; 1.6980x over previous
#include <cuda_runtime.h>
#include <cuda_bf16.h>
#include <math.h>
#include <stdint.h>

// Problem constants
#define B_   2
#define S_   2048
#define D_   1024
#define H_   16
#define DK_  64
#define MTOT (B_ * S_)   // 4096

// bf16 hi/lo buffers
__device__ __nv_bfloat16 g_xhi[(size_t)MTOT * D_];
__device__ __nv_bfloat16 g_xlo[(size_t)MTOT * D_];
__device__ __nv_bfloat16 g_whi[4][(size_t)D_ * D_];
__device__ __nv_bfloat16 g_wlo[4][(size_t)D_ * D_];
__device__ __nv_bfloat16 g_qhi[(size_t)MTOT * D_];
__device__ __nv_bfloat16 g_qlo[(size_t)MTOT * D_];
__device__ __nv_bfloat16 g_khi[(size_t)MTOT * D_];
__device__ __nv_bfloat16 g_klo[(size_t)MTOT * D_];
__device__ __nv_bfloat16 g_vhi[(size_t)MTOT * D_];
__device__ __nv_bfloat16 g_vlo[(size_t)MTOT * D_];
__device__ __nv_bfloat16 g_ohi[(size_t)MTOT * D_];
__device__ __nv_bfloat16 g_olo[(size_t)MTOT * D_];

// ============================================================================
// PTX helpers (base sm_100-safe)
// ============================================================================
__device__ __forceinline__ uint32_t smem_u32(const void* p) {
    return (uint32_t)__cvta_generic_to_shared(p);
}

#define CP_ASYNC16(dst, src) \
    asm volatile("cp.async.cg.shared.global [%0], [%1], 16;" :: "r"(dst), "l"(src))
#define CP_COMMIT() asm volatile("cp.async.commit_group;")
#define CP_WAIT1()  asm volatile("cp.async.wait_group 1;")
#define CP_WAIT0()  asm volatile("cp.async.wait_group 0;")

#define LDSM_X4(r, addr)                                                     \
    asm volatile("ldmatrix.sync.aligned.m8n8.x4.shared.b16 {%0,%1,%2,%3}, [%4];" \
                 : "=r"((r)[0]), "=r"((r)[1]), "=r"((r)[2]), "=r"((r)[3])    \
                 : "r"(addr))

#define LDSM_X4_T(r, addr)                                                   \
    asm volatile("ldmatrix.sync.aligned.m8n8.x4.trans.shared.b16 {%0,%1,%2,%3}, [%4];" \
                 : "=r"((r)[0]), "=r"((r)[1]), "=r"((r)[2]), "=r"((r)[3])    \
                 : "r"(addr))

#define MMA16816(d, a, b0v, b1v)                                             \
    asm volatile("mma.sync.aligned.m16n8k16.row.col.f32.bf16.bf16.f32 "     \
                 "{%0,%1,%2,%3}, {%4,%5,%6,%7}, {%8,%9}, {%0,%1,%2,%3};"    \
                 : "+f"((d)[0]), "+f"((d)[1]), "+f"((d)[2]), "+f"((d)[3])   \
                 : "r"((a)[0]), "r"((a)[1]), "r"((a)[2]), "r"((a)[3]),      \
                   "r"(b0v), "r"(b1v))

__device__ __forceinline__ uint32_t pack_bf16x2(float a, float b) {
    __nv_bfloat162 h = __floats2bfloat162_rn(a, b);
    return *(uint32_t*)&h;
}
// split a,b into bf16 hi pair + lo pair
__device__ __forceinline__ void split_pack(float a, float b, uint32_t& hi, uint32_t& lo) {
    __nv_bfloat162 h = __floats2bfloat162_rn(a, b);
    float2 hf = __bfloat1622float2(h);
    __nv_bfloat162 l = __floats2bfloat162_rn(a - hf.x, b - hf.y);
    hi = *(uint32_t*)&h;
    lo = *(uint32_t*)&l;
}

// ============================================================================
// hi/lo bf16 split kernel (for X and weights)
// ============================================================================
__global__ void split_bf16(const float* __restrict__ src,
                           __nv_bfloat16* __restrict__ hi,
                           __nv_bfloat16* __restrict__ lo, int n)
{
    int i = (blockIdx.x * blockDim.x + threadIdx.x) * 4;
    if (i >= n) return;
    float4 v = *(const float4*)(src + i);
    float f[4] = {v.x, v.y, v.z, v.w};
    __nv_bfloat162 h2[2], l2[2];
    #pragma unroll
    for (int p = 0; p < 2; p++) {
        __nv_bfloat16 h0 = __float2bfloat16(f[2*p]);
        __nv_bfloat16 h1 = __float2bfloat16(f[2*p+1]);
        __nv_bfloat16 l0 = __float2bfloat16(f[2*p]   - __bfloat162float(h0));
        __nv_bfloat16 l1 = __float2bfloat16(f[2*p+1] - __bfloat162float(h1));
        h2[p] = __nv_bfloat162(h0, h1);
        l2[p] = __nv_bfloat162(l0, l1);
    }
    *(uint2*)(hi + i) = *(uint2*)h2;
    *(uint2*)(lo + i) = *(uint2*)l2;
}

// ============================================================================
// mma.sync GEMM: C = A @ W^T + bias  (3-term bf16 split)
// mode 0: write fp32 Cf.   mode 1: write bf16 hi/lo of (C * scale).
// ============================================================================
#define GBK        32
#define TILE_B     8192
#define STAGE_B    (4 * TILE_B)
#define GSM_BYTES  (2 * STAGE_B + 256)

__global__ __launch_bounds__(256) void gemm_mma(
    const __nv_bfloat16* __restrict__ Ahi, const __nv_bfloat16* __restrict__ Alo,
    const __nv_bfloat16* __restrict__ Whi, const __nv_bfloat16* __restrict__ Wlo,
    const float* __restrict__ bias,
    float* __restrict__ Cf,
    __nv_bfloat16* __restrict__ Chi, __nv_bfloat16* __restrict__ Clo,
    float scale, int mode)
{
    extern __shared__ char dsm[];
    const uint32_t smbase = (smem_u32(dsm) + 127u) & ~127u;

    const int tid  = threadIdx.x;
    const int lane = tid & 31;
    const int wid  = tid >> 5;
    const int wm   = wid >> 2;
    const int wn   = wid & 3;
    const int row0 = blockIdx.y * 128;
    const int col0 = blockIdx.x * 128;

    const __nv_bfloat16* srcs[4] = {
        Ahi + (size_t)row0 * D_, Alo + (size_t)row0 * D_,
        Whi + (size_t)col0 * D_, Wlo + (size_t)col0 * D_
    };

    int l_tile[8], l_r[8], l_kk[8], l_g[8];
    uint32_t l_dst[8];
    #pragma unroll
    for (int t = 0; t < 8; t++) {
        int idx = tid + t * 256;
        l_tile[t] = idx >> 9;
        int i = idx & 511;
        l_r[t]  = i >> 2;
        l_kk[t] = (i >> 1) & 1;
        l_g[t]  = i & 1;
        int gsw = l_g[t] ^ ((l_r[t] >> 2) & 1);
        l_dst[t] = (uint32_t)(l_tile[t] * TILE_B + l_kk[t] * 4096 + l_r[t] * 32 + gsw * 16);
    }

    float acc[4][4][4];
    #pragma unroll
    for (int mi = 0; mi < 4; mi++)
        #pragma unroll
        for (int nj = 0; nj < 4; nj++)
            #pragma unroll
            for (int e = 0; e < 4; e++) acc[mi][nj][e] = 0.0f;

    const int lr = lane & 15;
    const int lg = lane >> 4;

    #pragma unroll
    for (int t = 0; t < 8; t++) {
        const __nv_bfloat16* gp = srcs[l_tile[t]] +
            (size_t)l_r[t] * D_ + l_kk[t] * 16 + l_g[t] * 8;
        CP_ASYNC16(smbase + l_dst[t], gp);
    }
    CP_COMMIT();

    const int NIT = D_ / GBK;
    for (int it = 0; it < NIT; it++) {
        const int s = it & 1;
        if (it + 1 < NIT) {
            const uint32_t sb = smbase + ((it + 1) & 1) * STAGE_B;
            #pragma unroll
            for (int t = 0; t < 8; t++) {
                const __nv_bfloat16* gp = srcs[l_tile[t]] +
                    (size_t)l_r[t] * D_ + (it + 1) * GBK + l_kk[t] * 16 + l_g[t] * 8;
                CP_ASYNC16(sb + l_dst[t], gp);
            }
            CP_COMMIT();
            CP_WAIT1();
        } else {
            CP_WAIT0();
        }
        __syncthreads();

        const uint32_t stg = smbase + s * STAGE_B;
        #pragma unroll
        for (int kk = 0; kk < 2; kk++) {
            uint32_t a_hi[4][4], a_lo[4][4];
            #pragma unroll
            for (int mi = 0; mi < 4; mi++) {
                int r = wm * 64 + mi * 16 + lr;
                uint32_t off = (uint32_t)(kk * 4096 + r * 32 + ((lg ^ ((r >> 2) & 1)) * 16));
                LDSM_X4(a_hi[mi], stg + 0 * TILE_B + off);
                LDSM_X4(a_lo[mi], stg + 1 * TILE_B + off);
            }
            uint32_t b_hi[2][4], b_lo[2][4];
            #pragma unroll
            for (int ni = 0; ni < 2; ni++) {
                int r = wn * 32 + ni * 16 + lr;
                uint32_t off = (uint32_t)(kk * 4096 + r * 32 + ((lg ^ ((r >> 2) & 1)) * 16));
                LDSM_X4(b_hi[ni], stg + 2 * TILE_B + off);
                LDSM_X4(b_lo[ni], stg + 3 * TILE_B + off);
            }
            #pragma unroll
            for (int mi = 0; mi < 4; mi++) {
                #pragma unroll
                for (int nj = 0; nj < 4; nj++) {
                    const int ni = nj >> 1, sel = nj & 1;
                    MMA16816(acc[mi][nj], a_hi[mi], b_hi[ni][sel], b_hi[ni][sel + 2]);
                    MMA16816(acc[mi][nj], a_hi[mi], b_lo[ni][sel], b_lo[ni][sel + 2]);
                    MMA16816(acc[mi][nj], a_lo[mi], b_hi[ni][sel], b_hi[ni][sel + 2]);
                }
            }
        }
        __syncthreads();
    }

    const int qr = lane >> 2;
    const int qc = (lane & 3) * 2;
    #pragma unroll
    for (int nj = 0; nj < 4; nj++) {
        const int c = col0 + wn * 32 + nj * 8 + qc;
        const float2 bv = *(const float2*)(bias + c);
        #pragma unroll
        for (int mi = 0; mi < 4; mi++) {
            const int r = row0 + wm * 64 + mi * 16 + qr;
            float v0 = acc[mi][nj][0] + bv.x, v1 = acc[mi][nj][1] + bv.y;
            float v2 = acc[mi][nj][2] + bv.x, v3 = acc[mi][nj][3] + bv.y;
            if (mode == 0) {
                *(float2*)(Cf + (size_t)r * D_ + c)       = make_float2(v0, v1);
                *(float2*)(Cf + (size_t)(r + 8) * D_ + c) = make_float2(v2, v3);
            } else {
                v0 *= scale; v1 *= scale; v2 *= scale; v3 *= scale;
                uint32_t h0, l0, h1, l1;
                split_pack(v0, v1, h0, l0);
                split_pack(v2, v3, h1, l1);
                *(uint32_t*)(Chi + (size_t)r * D_ + c)       = h0;
                *(uint32_t*)(Clo + (size_t)r * D_ + c)       = l0;
                *(uint32_t*)(Chi + (size_t)(r + 8) * D_ + c) = h1;
                *(uint32_t*)(Clo + (size_t)(r + 8) * D_ + c) = l1;
            }
        }
    }
}

// ============================================================================
// Tensor-core flash attention (causal), 3-term bf16 split throughout.
// CTA: 128 q-rows x 1 head, 8 warps (16 rows each). KV tiles of 64 keys,
// cp.async double-buffered. Q in registers; P stays in registers.
// Smem stage (32KB): Khi|Klo|Vhi|Vlo, each 64 rows x 128B, SW128-swizzled.
// ============================================================================
#define FQ    128
#define FKT   64
#define F_KHI 0
#define F_KLO 8192
#define F_VHI 16384
#define F_VLO 24576
#define F_STG 32768
#define FSM_BYTES (2 * F_STG + 128)

__global__ __launch_bounds__(256) void flash_mma(
    const __nv_bfloat16* __restrict__ Qhi, const __nv_bfloat16* __restrict__ Qlo,
    const __nv_bfloat16* __restrict__ Khi, const __nv_bfloat16* __restrict__ Klo,
    const __nv_bfloat16* __restrict__ Vhi, const __nv_bfloat16* __restrict__ Vlo,
    __nv_bfloat16* __restrict__ Ohi, __nv_bfloat16* __restrict__ Olo)
{
    extern __shared__ char dsm[];
    const uint32_t smbase = (smem_u32(dsm) + 127u) & ~127u;

    const int tid  = threadIdx.x;
    const int lane = tid & 31;
    const int w    = tid >> 5;
    const int qb   = (int)gridDim.x - 1 - (int)blockIdx.x;  // big tiles first
    const int h    = blockIdx.y;
    const int b    = blockIdx.z;
    const int q0   = qb * FQ;

    // ---- load Q tile (hi -> [0,16K), lo -> [16K,32K) of stage0), ldmatrix to regs
    {
        #pragma unroll
        for (int t = 0; t < 8; t++) {
            int idx = tid + t * 256;
            int mat = idx >> 10;          // 0=hi, 1=lo
            int i   = idx & 1023;
            int row = i >> 3, g = i & 7;
            const __nv_bfloat16* src = (mat ? Qlo : Qhi) +
                (size_t)(b * S_ + q0 + row) * D_ + h * DK_ + g * 8;
            uint32_t dst = smbase + mat * 16384 + row * 128 + ((g ^ (row & 7)) << 4);
            CP_ASYNC16(dst, src);
        }
        CP_COMMIT();
        CP_WAIT0();
        __syncthreads();
    }

    uint32_t qa_h[4][4], qa_l[4][4];
    #pragma unroll
    for (int c = 0; c < 4; c++) {
        int row = w * 16 + (lane & 15);
        int colb = c * 32 + (lane >> 4) * 16;
        uint32_t off = row * 128 + (colb ^ ((row & 7) << 4));
        LDSM_X4(qa_h[c], smbase + off);
        LDSM_X4(qa_l[c], smbase + 16384 + off);
    }
    __syncthreads();   // Q staging area now free for KV

    const int nkt = 2 * (qb + 1);

    // KV tile loader: 8 cp.async per thread
    const __nv_bfloat16* kvsrc[4] = {Khi, Klo, Vhi, Vlo};
    auto load_kv = [&](int t, uint32_t stg) {
        #pragma unroll
        for (int u = 0; u < 8; u++) {
            int idx = tid + u * 256;
            int mat = idx >> 9;            // 0..3
            int i   = idx & 511;
            int row = i >> 3, g = i & 7;
            const __nv_bfloat16* src = kvsrc[mat] +
                (size_t)(b * S_ + t * FKT + row) * D_ + h * DK_ + g * 8;
            uint32_t dst = stg + mat * 8192 + row * 128 + ((g ^ (row & 7)) << 4);
            CP_ASYNC16(dst, src);
        }
    };

    load_kv(0, smbase);
    CP_COMMIT();

    float m_r[2] = {-1e30f, -1e30f};
    float l_r[2] = {0.0f, 0.0f};
    float oacc[8][4];
    #pragma unroll
    for (int j = 0; j < 8; j++)
        #pragma unroll
        for (int e = 0; e < 4; e++) oacc[j][e] = 0.0f;

    const int rg0 = q0 + w * 16 + (lane >> 2);   // global q row (regs 0,1)

    for (int t = 0; t < nkt; t++) {
        if (t + 1 < nkt) {
            load_kv(t + 1, smbase + ((t + 1) & 1) * F_STG);
            CP_COMMIT();
            CP_WAIT1();
        } else {
            CP_WAIT0();
        }
        __syncthreads();

        const uint32_t stg = smbase + (t & 1) * F_STG;

        // ---- scores S = Q K^T (16 x 64 per warp), 3-term split
        float sacc[8][4];
        #pragma unroll
        for (int j = 0; j < 8; j++)
            #pragma unroll
            for (int e = 0; e < 4; e++) sacc[j][e] = 0.0f;

        #pragma unroll
        for (int c = 0; c < 4; c++) {
            #pragma unroll
            for (int ng = 0; ng < 4; ng++) {
                int row = ng * 16 + (lane & 15);
                int colb = c * 32 + (lane >> 4) * 16;
                uint32_t off = row * 128 + (colb ^ ((row & 7) << 4));
                uint32_t kh[4], kl[4];
                LDSM_X4(kh, stg + F_KHI + off);
                LDSM_X4(kl, stg + F_KLO + off);
                #pragma unroll
                for (int sel = 0; sel < 2; sel++) {
                    const int j = ng * 2 + sel;
                    MMA16816(sacc[j], qa_h[c], kh[sel], kh[sel + 2]);
                    MMA16816(sacc[j], qa_h[c], kl[sel], kl[sel + 2]);
                    MMA16816(sacc[j], qa_l[c], kh[sel], kh[sel + 2]);
                }
            }
        }

        // ---- causal mask (only near-diagonal tiles need it)
        const int kt0 = t * FKT;
        if (kt0 + FKT - 1 > q0 + w * 16) {
            #pragma unroll
            for (int j = 0; j < 8; j++) {
                int kc = kt0 + j * 8 + (lane & 3) * 2;
                if (kc     > rg0)     sacc[j][0] = -1e30f;
                if (kc + 1 > rg0)     sacc[j][1] = -1e30f;
                if (kc     > rg0 + 8) sacc[j][2] = -1e30f;
                if (kc + 1 > rg0 + 8) sacc[j][3] = -1e30f;
            }
        }

        // ---- online softmax (rows r and r+8)
        float tm0 = -1e30f, tm1 = -1e30f;
        #pragma unroll
        for (int j = 0; j < 8; j++) {
            tm0 = fmaxf(tm0, fmaxf(sacc[j][0], sacc[j][1]));
            tm1 = fmaxf(tm1, fmaxf(sacc[j][2], sacc[j][3]));
        }
        tm0 = fmaxf(tm0, __shfl_xor_sync(0xffffffffu, tm0, 1));
        tm0 = fmaxf(tm0, __shfl_xor_sync(0xffffffffu, tm0, 2));
        tm1 = fmaxf(tm1, __shfl_xor_sync(0xffffffffu, tm1, 1));
        tm1 = fmaxf(tm1, __shfl_xor_sync(0xffffffffu, tm1, 2));

        float mn0 = fmaxf(m_r[0], tm0);
        float mn1 = fmaxf(m_r[1], tm1);
        float a0 = __expf(m_r[0] - mn0);
        float a1 = __expf(m_r[1] - mn1);
        m_r[0] = mn0; m_r[1] = mn1;

        float ps0 = 0.0f, ps1 = 0.0f;
        #pragma unroll
        for (int j = 0; j < 8; j++) {
            sacc[j][0] = __expf(sacc[j][0] - mn0);
            sacc[j][1] = __expf(sacc[j][1] - mn0);
            sacc[j][2] = __expf(sacc[j][2] - mn1);
            sacc[j][3] = __expf(sacc[j][3] - mn1);
            ps0 += sacc[j][0] + sacc[j][1];
            ps1 += sacc[j][2] + sacc[j][3];
        }
        ps0 += __shfl_xor_sync(0xffffffffu, ps0, 1);
        ps0 += __shfl_xor_sync(0xffffffffu, ps0, 2);
        ps1 += __shfl_xor_sync(0xffffffffu, ps1, 1);
        ps1 += __shfl_xor_sync(0xffffffffu, ps1, 2);
        l_r[0] = l_r[0] * a0 + ps0;
        l_r[1] = l_r[1] * a1 + ps1;

        #pragma unroll
        for (int j = 0; j < 8; j++) {
            oacc[j][0] *= a0; oacc[j][1] *= a0;
            oacc[j][2] *= a1; oacc[j][3] *= a1;
        }

        // ---- PV: oacc += P @ V, 3-term split, P from registers
        #pragma unroll
        for (int tk = 0; tk < 4; tk++) {
            uint32_t pah[4], pal[4];
            split_pack(sacc[2*tk][0],   sacc[2*tk][1],   pah[0], pal[0]);
            split_pack(sacc[2*tk][2],   sacc[2*tk][3],   pah[1], pal[1]);
            split_pack(sacc[2*tk+1][0], sacc[2*tk+1][1], pah[2], pal[2]);
            split_pack(sacc[2*tk+1][2], sacc[2*tk+1][3], pah[3], pal[3]);

            #pragma unroll
            for (int dp = 0; dp < 4; dp++) {
                // ldmatrix.trans lane addressing: 4 sub-matrices of V[16k x 16d]
                int sub = lane >> 3, i8 = lane & 7;
                int row = tk * 16 + (sub & 1) * 8 + i8;
                int colb = dp * 32 + (sub >> 1) * 16;
                uint32_t off = row * 128 + (colb ^ ((row & 7) << 4));
                uint32_t vh[4], vl[4];
                LDSM_X4_T(vh, stg + F_VHI + off);
                LDSM_X4_T(vl, stg + F_VLO + off);
                #pragma unroll
                for (int sel = 0; sel < 2; sel++) {
                    const int j = dp * 2 + sel;
                    MMA16816(oacc[j], pah, vh[sel*2], vh[sel*2+1]);
                    MMA16816(oacc[j], pah, vl[sel*2], vl[sel*2+1]);
                    MMA16816(oacc[j], pal, vh[sel*2], vh[sel*2+1]);
                }
            }
        }
        __syncthreads();   // compute done before next prefetch overwrites
    }

    // ---- epilogue: normalize, split to hi/lo bf16, store
    const float inv0 = 1.0f / l_r[0];
    const float inv1 = 1.0f / l_r[1];
    const size_t r0 = (size_t)(b * S_) + rg0;
    const size_t r1 = r0 + 8;
    #pragma unroll
    for (int j = 0; j < 8; j++) {
        int col = h * DK_ + j * 8 + (lane & 3) * 2;
        uint32_t h0, l0, h1, l1;
        split_pack(oacc[j][0] * inv0, oacc[j][1] * inv0, h0, l0);
        split_pack(oacc[j][2] * inv1, oacc[j][3] * inv1, h1, l1);
        *(uint32_t*)(Ohi + r0 * D_ + col) = h0;
        *(uint32_t*)(Olo + r0 * D_ + col) = l0;
        *(uint32_t*)(Ohi + r1 * D_ + col) = h1;
        *(uint32_t*)(Olo + r1 * D_ + col) = l1;
    }
}

// ============================================================================
// Launch
// ============================================================================
extern "C" void kernel_launch(void* const* d_in, const int* in_sizes, int n_in,
                              void* d_out, int out_size)
{
    const float* X  = (const float*)d_in[0];
    const float* Wq = (const float*)d_in[1];
    const float* bq = (const float*)d_in[2];
    const float* Wk = (const float*)d_in[3];
    const float* bk = (const float*)d_in[4];
    const float* Wv = (const float*)d_in[5];
    const float* bv = (const float*)d_in[6];
    const float* Wo = (const float*)d_in[7];
    const float* bo = (const float*)d_in[8];
    float* out = (float*)d_out;

    __nv_bfloat16 *xhi, *xlo, *whi, *wlo;
    __nv_bfloat16 *qhi, *qlo, *khi, *klo, *vhi, *vlo, *ohi, *olo;
    cudaGetSymbolAddress((void**)&xhi, g_xhi);
    cudaGetSymbolAddress((void**)&xlo, g_xlo);
    cudaGetSymbolAddress((void**)&whi, g_whi);
    cudaGetSymbolAddress((void**)&wlo, g_wlo);
    cudaGetSymbolAddress((void**)&qhi, g_qhi);
    cudaGetSymbolAddress((void**)&qlo, g_qlo);
    cudaGetSymbolAddress((void**)&khi, g_khi);
    cudaGetSymbolAddress((void**)&klo, g_klo);
    cudaGetSymbolAddress((void**)&vhi, g_vhi);
    cudaGetSymbolAddress((void**)&vlo, g_vlo);
    cudaGetSymbolAddress((void**)&ohi, g_ohi);
    cudaGetSymbolAddress((void**)&olo, g_olo);

    cudaFuncSetAttribute(gemm_mma, cudaFuncAttributeMaxDynamicSharedMemorySize, GSM_BYTES);
    cudaFuncSetAttribute(flash_mma, cudaFuncAttributeMaxDynamicSharedMemorySize, FSM_BYTES);

    const size_t WSZ = (size_t)D_ * D_;
    const int nX = MTOT * D_;
    const int nW = D_ * D_;

    split_bf16<<<nX / 1024, 256>>>(X, xhi, xlo, nX);
    split_bf16<<<nW / 1024, 256>>>(Wq, whi + 0 * WSZ, wlo + 0 * WSZ, nW);
    split_bf16<<<nW / 1024, 256>>>(Wk, whi + 1 * WSZ, wlo + 1 * WSZ, nW);
    split_bf16<<<nW / 1024, 256>>>(Wv, whi + 2 * WSZ, wlo + 2 * WSZ, nW);
    split_bf16<<<nW / 1024, 256>>>(Wo, whi + 3 * WSZ, wlo + 3 * WSZ, nW);

    dim3 gg(D_ / 128, MTOT / 128);   // (8, 32)
    const float qscale = 0.125f;     // 1/sqrt(DK)
    gemm_mma<<<gg, 256, GSM_BYTES>>>(xhi, xlo, whi + 0 * WSZ, wlo + 0 * WSZ, bq,
                                     nullptr, qhi, qlo, qscale, 1);
    gemm_mma<<<gg, 256, GSM_BYTES>>>(xhi, xlo, whi + 1 * WSZ, wlo + 1 * WSZ, bk,
                                     nullptr, khi, klo, 1.0f, 1);
    gemm_mma<<<gg, 256, GSM_BYTES>>>(xhi, xlo, whi + 2 * WSZ, wlo + 2 * WSZ, bv,
                                     nullptr, vhi, vlo, 1.0f, 1);

    flash_mma<<<dim3(S_ / FQ, H_, B_), 256, FSM_BYTES>>>(qhi, qlo, khi, klo,
                                                         vhi, vlo, ohi, olo);

    gemm_mma<<<gg, 256, GSM_BYTES>>>(ohi, olo, whi + 3 * WSZ, wlo + 3 * WSZ, bo,
                                     out, nullptr, nullptr, 1.0f, 0);
}